// round 1
// baseline (speedup 1.0000x reference)
#include <cuda_runtime.h>
#include <math.h>

#define NB   2048
#define NT   60
#define NDL  100
#define ND   512
#define NH   256

// ---------------- scratch (device globals; no allocation allowed) ----------------
__device__ float g_h0[NB * ND];               // fc output
__device__ float g_stats[2 * ND];             // mu, var
__device__ float g_h[NB * ND];                // bn + lrelu output
__device__ float g_gates[2][NB * 3 * NH];     // precomputed x@Wih^T + bih per dir
__device__ float g_state[2][2][NB * NH];      // [dir][pingpong] GRU hidden state
__device__ float g_gru[NB * NT * 2 * NH];     // concat(gf, gb) [B,T,512]
__device__ float g_s[NB * NT];                // attention logits
__device__ float g_c[NB * 2 * NH];            // context vector

// ---------------- generic tiled GEMM: C[M,N] = A[M,K] @ Bw[N,K]^T + bias[N] -------
// M, N must be multiples of 64 (2048 / 512 / 768 all qualify); K arbitrary.
__global__ void __launch_bounds__(256) gemm_bias(
    const float* __restrict__ A, const float* __restrict__ Bw,
    const float* __restrict__ bias, float* __restrict__ C,
    int M, int N, int K)
{
    __shared__ float As[16][65];
    __shared__ float Bs[16][65];
    int tid = threadIdx.x;
    int tx = tid & 15, ty = tid >> 4;
    int m0 = blockIdx.y * 64, n0 = blockIdx.x * 64;
    float acc[4][4] = {};
    for (int k0 = 0; k0 < K; k0 += 16) {
        #pragma unroll
        for (int i = 0; i < 4; i++) {
            int lin = tid + i * 256;
            int m = lin >> 4, k = lin & 15;
            As[k][m] = (k0 + k < K) ? A[(m0 + m) * K + k0 + k] : 0.f;
        }
        #pragma unroll
        for (int i = 0; i < 4; i++) {
            int lin = tid + i * 256;
            int n = lin >> 4, k = lin & 15;
            Bs[k][n] = (k0 + k < K) ? Bw[(n0 + n) * K + k0 + k] : 0.f;
        }
        __syncthreads();
        #pragma unroll
        for (int kk = 0; kk < 16; kk++) {
            float a[4], b[4];
            #pragma unroll
            for (int i = 0; i < 4; i++) a[i] = As[kk][ty * 4 + i];
            #pragma unroll
            for (int j = 0; j < 4; j++) b[j] = Bs[kk][tx * 4 + j];
            #pragma unroll
            for (int i = 0; i < 4; i++)
                #pragma unroll
                for (int j = 0; j < 4; j++) acc[i][j] += a[i] * b[j];
        }
        __syncthreads();
    }
    #pragma unroll
    for (int i = 0; i < 4; i++) {
        int m = m0 + ty * 4 + i;
        #pragma unroll
        for (int j = 0; j < 4; j++) {
            int n = n0 + tx * 4 + j;
            C[m * N + n] = acc[i][j] + bias[n];
        }
    }
}

// ---------------- batchnorm statistics (training mode, over batch dim) ----------
__global__ void __launch_bounds__(256) bn_stats()
{
    int c = blockIdx.x;     // 512 columns
    float s = 0.f, s2 = 0.f;
    for (int r = threadIdx.x; r < NB; r += 256) {
        float v = g_h0[r * ND + c];
        s += v; s2 += v * v;
    }
    __shared__ float sh[256], sh2[256];
    sh[threadIdx.x] = s; sh2[threadIdx.x] = s2;
    __syncthreads();
    for (int o = 128; o > 0; o >>= 1) {
        if (threadIdx.x < o) {
            sh[threadIdx.x]  += sh[threadIdx.x + o];
            sh2[threadIdx.x] += sh2[threadIdx.x + o];
        }
        __syncthreads();
    }
    if (threadIdx.x == 0) {
        float mu = sh[0] / (float)NB;
        g_stats[c] = mu;
        g_stats[ND + c] = sh2[0] / (float)NB - mu * mu;
    }
}

__global__ void __launch_bounds__(256) bn_apply(
    const float* __restrict__ bn_g, const float* __restrict__ bn_b)
{
    int i = blockIdx.x * 256 + threadIdx.x;     // NB*ND threads
    int c = i & (ND - 1);
    float mu = g_stats[c], var = g_stats[ND + c];
    float v = (g_h0[i] - mu) * rsqrtf(var + 1e-5f) * bn_g[c] + bn_b[c];
    g_h[i] = (v >= 0.f) ? v : 0.2f * v;
}

// ---------------- fused GRU step: gh = h@Whh^T + bhh, gates, state update -------
// Grid: (8 n-tiles of 32, 16 m-tiles of 128, 2 dirs). Each block computes the
// three gate chunks (r,z,n) for its 128x32 (m,j) tile and updates the state.
__global__ void __launch_bounds__(256) gru_step(
    const float* __restrict__ Whh_f, const float* __restrict__ bhh_f,
    const float* __restrict__ Whh_b, const float* __restrict__ bhh_b,
    int t)
{
    int dir = blockIdx.z;
    const float* Whh = dir ? Whh_b : Whh_f;
    const float* bhh = dir ? bhh_b : bhh_f;
    const float* gin = g_gates[dir];
    int src = t & 1, dst = src ^ 1;
    const float* hsrc = g_state[dir][src];
    float*       hdst = g_state[dir][dst];

    __shared__ float As[16][132];   // [k][m]
    __shared__ float Bs[16][98];    // [k][g*32 + j]
    int tid = threadIdx.x;
    int tx = tid & 15, ty = tid >> 4;
    int m0 = blockIdx.y * 128;
    int n0 = blockIdx.x * 32;

    float acc[8][6] = {};   // [row][gate*2 + c]

    for (int k0 = 0; k0 < NH; k0 += 16) {
        if (t == 0) {
            #pragma unroll
            for (int i = 0; i < 8; i++) {
                int lin = tid + i * 256;
                As[lin & 15][lin >> 4] = 0.f;
            }
        } else {
            #pragma unroll
            for (int i = 0; i < 2; i++) {   // float4 loads: 512 float4 / 256 thr
                int lin4 = tid + i * 256;
                int m = lin4 >> 2, kq = lin4 & 3;
                float4 v = *(const float4*)&hsrc[(m0 + m) * NH + k0 + kq * 4];
                As[kq * 4 + 0][m] = v.x;
                As[kq * 4 + 1][m] = v.y;
                As[kq * 4 + 2][m] = v.z;
                As[kq * 4 + 3][m] = v.w;
            }
        }
        #pragma unroll
        for (int i = 0; i < 6; i++) {       // 96 rows x 16 = 1536 / 256 thr
            int lin = tid + i * 256;
            int n = lin >> 4, k = lin & 15;   // n in [0,96)
            int gg = n >> 5, j = n & 31;
            Bs[k][n] = Whh[(gg * NH + n0 + j) * NH + k0 + k];
        }
        __syncthreads();
        #pragma unroll
        for (int kk = 0; kk < 16; kk++) {
            float a[8], b[6];
            #pragma unroll
            for (int i = 0; i < 8; i++) a[i] = As[kk][ty * 8 + i];
            #pragma unroll
            for (int g = 0; g < 3; g++) {
                b[g * 2 + 0] = Bs[kk][g * 32 + tx * 2 + 0];
                b[g * 2 + 1] = Bs[kk][g * 32 + tx * 2 + 1];
            }
            #pragma unroll
            for (int i = 0; i < 8; i++)
                #pragma unroll
                for (int j = 0; j < 6; j++) acc[i][j] += a[i] * b[j];
        }
        __syncthreads();
    }

    int tt = dir ? (NT - 1 - t) : t;
    #pragma unroll
    for (int i = 0; i < 8; i++) {
        int m = m0 + ty * 8 + i;
        #pragma unroll
        for (int c = 0; c < 2; c++) {
            int j = n0 + tx * 2 + c;
            float ghr = acc[i][0 * 2 + c] + bhh[j];
            float ghz = acc[i][1 * 2 + c] + bhh[NH + j];
            float ghn = acc[i][2 * 2 + c] + bhh[2 * NH + j];
            float gr = gin[m * 3 * NH + j];
            float gz = gin[m * 3 * NH + NH + j];
            float gn = gin[m * 3 * NH + 2 * NH + j];
            float r = 1.f / (1.f + expf(-(gr + ghr)));
            float z = 1.f / (1.f + expf(-(gz + ghz)));
            float n = tanhf(gn + r * ghn);
            float hold = (t == 0) ? 0.f : hsrc[m * NH + j];
            float hn = (1.f - z) * n + z * hold;
            hdst[m * NH + j] = hn;
            g_gru[(m * NT + tt) * (2 * NH) + dir * NH + j] = hn;
        }
    }
}

// ---------------- attention scores: s = W2 . tanh(W1 @ gru_row + b1) ------------
// Treated as GEMM M=B*T (rows of g_gru), N=256, K=512, fused epilogue + row reduce.
__global__ void __launch_bounds__(256) attn_score(
    const float* __restrict__ W1, const float* __restrict__ b1,
    const float* __restrict__ W2)
{
    __shared__ float As[16][34];
    __shared__ float Bs[16][256];
    int tid = threadIdx.x;
    int tx = tid & 31, ty = tid >> 5;    // tx = lane, ty = warp
    int m0 = blockIdx.x * 32;
    float acc[4][8] = {};
    for (int k0 = 0; k0 < 512; k0 += 16) {
        #pragma unroll
        for (int i = 0; i < 2; i++) {
            int lin = tid + i * 256;
            int m = lin >> 4, k = lin & 15;
            As[k][m] = g_gru[(m0 + m) * 512 + k0 + k];
        }
        #pragma unroll
        for (int i = 0; i < 4; i++) {       // 1024 float4 / 256 thr
            int lin4 = tid + i * 256;
            int n = lin4 >> 2, kq = lin4 & 3;
            float4 v = *(const float4*)&W1[n * 512 + k0 + kq * 4];
            Bs[kq * 4 + 0][n] = v.x;
            Bs[kq * 4 + 1][n] = v.y;
            Bs[kq * 4 + 2][n] = v.z;
            Bs[kq * 4 + 3][n] = v.w;
        }
        __syncthreads();
        #pragma unroll
        for (int kk = 0; kk < 16; kk++) {
            float a[4], b[8];
            #pragma unroll
            for (int r = 0; r < 4; r++) a[r] = As[kk][ty * 4 + r];
            #pragma unroll
            for (int c = 0; c < 8; c++) b[c] = Bs[kk][tx + c * 32];
            #pragma unroll
            for (int r = 0; r < 4; r++)
                #pragma unroll
                for (int c = 0; c < 8; c++) acc[r][c] += a[r] * b[c];
        }
        __syncthreads();
    }
    float partial[4];
    #pragma unroll
    for (int r = 0; r < 4; r++) {
        float s = 0.f;
        #pragma unroll
        for (int c = 0; c < 8; c++) {
            int col = tx + c * 32;
            s += tanhf(acc[r][c] + b1[col]) * W2[col];
        }
        partial[r] = s;
    }
    #pragma unroll
    for (int o = 16; o > 0; o >>= 1)
        #pragma unroll
        for (int r = 0; r < 4; r++)
            partial[r] += __shfl_xor_sync(0xffffffffu, partial[r], o);
    if (tx == 0) {
        #pragma unroll
        for (int r = 0; r < 4; r++) g_s[m0 + ty * 4 + r] = partial[r];
    }
}

// ---------------- softmax over time + context vector ----------------------------
__global__ void __launch_bounds__(256) softmax_ctx()
{
    int b = blockIdx.x;
    __shared__ float w[NT];
    int tid = threadIdx.x;
    if (tid == 0) {
        float mx = -1e30f;
        for (int t = 0; t < NT; t++) {
            float v = g_s[b * NT + t];
            if (v > mx) mx = v;
            w[t] = v;
        }
        float s = 0.f;
        for (int t = 0; t < NT; t++) { w[t] = expf(w[t] - mx); s += w[t]; }
        float inv = 1.f / s;
        for (int t = 0; t < NT; t++) w[t] *= inv;
    }
    __syncthreads();
    for (int d = tid; d < 2 * NH; d += 256) {
        float s = 0.f;
        for (int t = 0; t < NT; t++)
            s += w[t] * g_gru[(b * NT + t) * (2 * NH) + d];
        g_c[b * 2 * NH + d] = s;
    }
}

// ---------------- joint head + forward kinematics --------------------------------
__global__ void __launch_bounds__(256) joints_fk(
    const float* __restrict__ jW, const float* __restrict__ jb,
    float* __restrict__ out)
{
    int w = blockIdx.x * 8 + (threadIdx.x >> 5);    // one warp per (b,t)
    int lane = threadIdx.x & 31;
    if (w >= NB * NT) return;
    int b = w / NT;
    const float* row  = &g_gru[w * 512];
    const float* crow = &g_c[b * 512];
    float p[6] = {};
    #pragma unroll
    for (int k = 0; k < 16; k++) {
        int d = lane + k * 32;
        float x = row[d] + crow[d];
        #pragma unroll
        for (int j = 0; j < 6; j++) p[j] += x * jW[j * 512 + d];
    }
    #pragma unroll
    for (int o = 16; o > 0; o >>= 1)
        #pragma unroll
        for (int j = 0; j < 6; j++) p[j] += __shfl_xor_sync(0xffffffffu, p[j], o);
    if (lane != 0) return;

    const float LO[6] = {-3.1416f, -1.5708f, -3.1416f, -2.6f, -1.5708f, -1.2f};
    const float UP[6] = { 3.1416f,  1.5708f,  3.1416f,  0.1f,  1.5708f,  1.2f};
    float th[6];
    #pragma unroll
    for (int j = 0; j < 6; j++)
        th[j] = (p[j] + jb[j]) * (UP[j] - LO[j]) + LO[j];

    // rotation columns
    float c0[3] = {1.f, 0.f, 0.f}, c1[3] = {0.f, 1.f, 0.f}, c2[3] = {0.f, 0.f, 1.f};
    float px = 0.f, py = 0.f, pz = 0.10f;   // after joint-0 offset (R = I)
    float sh2x = 0.f, sh2y = 0.f, sh2z = 0.10f;

    float c, s, tmp;
    // j0: rotZ
    c = cosf(th[0]); s = sinf(th[0]);
    #pragma unroll
    for (int i = 0; i < 3; i++) { tmp = c*c0[i] + s*c1[i]; c1[i] = c*c1[i] - s*c0[i]; c0[i] = tmp; }
    // j1: offset 0 -> pos1 = shoulder2 = (0,0,0.1); rotX
    c = cosf(th[1]); s = sinf(th[1]);
    #pragma unroll
    for (int i = 0; i < 3; i++) { tmp = c*c1[i] + s*c2[i]; c2[i] = c*c2[i] - s*c1[i]; c1[i] = tmp; }
    // j2: rotY
    c = cosf(th[2]); s = sinf(th[2]);
    #pragma unroll
    for (int i = 0; i < 3; i++) { tmp = c*c0[i] - s*c2[i]; c2[i] = c*c2[i] + s*c0[i]; c0[i] = tmp; }
    // j3: offset (0,-0.25,0) -> forearm; rotX
    px -= 0.25f * c1[0]; py -= 0.25f * c1[1]; pz -= 0.25f * c1[2];
    float fax = px, fay = py, faz = pz;
    c = cosf(th[3]); s = sinf(th[3]);
    #pragma unroll
    for (int i = 0; i < 3; i++) { tmp = c*c1[i] + s*c2[i]; c2[i] = c*c2[i] - s*c1[i]; c1[i] = tmp; }
    // j4: rotY
    c = cosf(th[4]); s = sinf(th[4]);
    #pragma unroll
    for (int i = 0; i < 3; i++) { tmp = c*c0[i] - s*c2[i]; c2[i] = c*c2[i] + s*c0[i]; c0[i] = tmp; }
    // j5: offset (0,-0.25,0) -> wrist; rotX
    px -= 0.25f * c1[0]; py -= 0.25f * c1[1]; pz -= 0.25f * c1[2];
    float wx = px, wy = py, wz = pz;
    c = cosf(th[5]); s = sinf(th[5]);
    #pragma unroll
    for (int i = 0; i < 3; i++) { tmp = c*c1[i] + s*c2[i]; c2[i] = c*c2[i] - s*c1[i]; c1[i] = tmp; }

    // fingers (final R)
    float f1x = wx - 0.08f*c1[0] + 0.02f*c2[0];
    float f1y = wy - 0.08f*c1[1] + 0.02f*c2[1];
    float f1z = wz - 0.08f*c1[2] + 0.02f*c2[2];
    float f4x = wx - 0.08f*c1[0] - 0.02f*c2[0];
    float f4y = wy - 0.08f*c1[1] - 0.02f*c2[1];
    float f4z = wz - 0.08f*c1[2] - 0.02f*c2[2];

    float d1x = sh2x - fax, d1y = sh2y - fay, d1z = sh2z - faz;
    float d2x = wx - fax,   d2y = wy - fay,   d2z = wz - faz;
    float bodyL = 0.5f * (sqrtf(d1x*d1x + d1y*d1y + d1z*d1z)
                        + sqrtf(d2x*d2x + d2y*d2y + d2z*d2z));
    float inv = 1.f / bodyL;

    float* o = out + (long)w * 9;
    o[0] = (wx  - sh2x) * inv; o[1] = (wy  - sh2y) * inv; o[2] = (wz  - sh2z) * inv;
    o[3] = (f1x - sh2x) * inv; o[4] = (f1y - sh2y) * inv; o[5] = (f1z - sh2z) * inv;
    o[6] = (f4x - sh2x) * inv; o[7] = (f4y - sh2y) * inv; o[8] = (f4z - sh2z) * inv;
}

// ---------------- host launcher ---------------------------------------------------
extern "C" void kernel_launch(void* const* d_in, const int* in_sizes, int n_in,
                              void* d_out, int out_size)
{
    const float* z       = (const float*)d_in[0];
    const float* W_fc    = (const float*)d_in[1];
    const float* b_fc    = (const float*)d_in[2];
    const float* bn_g    = (const float*)d_in[3];
    const float* bn_b    = (const float*)d_in[4];
    const float* Wih_f   = (const float*)d_in[5];
    const float* Whh_f   = (const float*)d_in[6];
    const float* bih_f   = (const float*)d_in[7];
    const float* bhh_f   = (const float*)d_in[8];
    const float* Wih_b   = (const float*)d_in[9];
    const float* Whh_b   = (const float*)d_in[10];
    const float* bih_b   = (const float*)d_in[11];
    const float* bhh_b   = (const float*)d_in[12];
    const float* attn_W1 = (const float*)d_in[13];
    const float* attn_b1 = (const float*)d_in[14];
    const float* attn_W2 = (const float*)d_in[15];
    const float* joint_W = (const float*)d_in[16];
    const float* joint_b = (const float*)d_in[17];
    float* out = (float*)d_out;

    void *p_h0, *p_h, *p_gates;
    cudaGetSymbolAddress(&p_h0, g_h0);
    cudaGetSymbolAddress(&p_h, g_h);
    cudaGetSymbolAddress(&p_gates, g_gates);
    float* f_h0 = (float*)p_h0;
    float* f_h = (float*)p_h;
    float* f_gates = (float*)p_gates;

    // 1) fc: h0 = z @ W_fc^T + b_fc   [2048,512], K=100
    gemm_bias<<<dim3(ND / 64, NB / 64), 256>>>(z, W_fc, b_fc, f_h0, NB, ND, NDL);
    // 2) batch stats
    bn_stats<<<ND, 256>>>();
    // 3) bn + leaky relu
    bn_apply<<<NB * ND / 256, 256>>>(bn_g, bn_b);
    // 4) precompute input gates (x is constant over time!)  [2048,768] each dir
    gemm_bias<<<dim3(3 * NH / 64, NB / 64), 256>>>(f_h, Wih_f, bih_f, f_gates,              NB, 3 * NH, ND);
    gemm_bias<<<dim3(3 * NH / 64, NB / 64), 256>>>(f_h, Wih_b, bih_b, f_gates + NB * 3 * NH, NB, 3 * NH, ND);
    // 5) GRU recurrence, both directions concurrently per step
    for (int t = 0; t < NT; t++)
        gru_step<<<dim3(NH / 32, NB / 128, 2), 256>>>(Whh_f, bhh_f, Whh_b, bhh_b, t);
    // 6) attention scores
    attn_score<<<NB * NT / 32, 256>>>(attn_W1, attn_b1, attn_W2);
    // 7) softmax over time + context
    softmax_ctx<<<NB, 256>>>();
    // 8) joint head + FK
    joints_fk<<<NB * NT / 8, 256>>>(joint_W, joint_b, out);
}

// round 3
// speedup vs baseline: 1.1631x; 1.1631x over previous
#include <cuda_runtime.h>
#include <cuda_bf16.h>
#include <math.h>
#include <stdint.h>

#define NB   2048
#define NT   60
#define NDL  100
#define ND   512
#define NH   256

// ---------------- scratch (device globals) ----------------
__device__ float g_h0[NB * ND];
__device__ float g_stats[2 * ND];
__device__ float g_h[NB * ND];
__device__ float g_gates[2][NB * 3 * NH];          // x@Wih^T + bih (fp32)
__device__ float g_sf[2][2][NB * NH];              // fp32 GRU state [dir][pingpong]
__device__ __nv_bfloat16 g_shh[2][2][NB * NH];     // bf16 hi copy of state
__device__ __nv_bfloat16 g_shl[2][2][NB * NH];     // bf16 lo copy of state
__device__ __nv_bfloat16 g_whh[2][3 * NH * NH];    // Whh split hi
__device__ __nv_bfloat16 g_whl[2][3 * NH * NH];    // Whh split lo
__device__ float g_gru[NB * NT * 2 * NH];          // concat(gf,gb) fp32 [B,T,512]
__device__ float g_s[NB * NT];
__device__ float g_c[NB * 2 * NH];

__device__ __forceinline__ void bsplit(float v, __nv_bfloat16& h, __nv_bfloat16& l) {
    h = __float2bfloat16(v);
    l = __float2bfloat16(v - __bfloat162float(h));
}

__device__ __forceinline__ void mma16816(float& d0, float& d1, float& d2, float& d3,
    uint32_t a0, uint32_t a1, uint32_t a2, uint32_t a3, uint32_t b0, uint32_t b1)
{
    asm volatile("mma.sync.aligned.m16n8k16.row.col.f32.bf16.bf16.f32 "
                 "{%0,%1,%2,%3},{%4,%5,%6,%7},{%8,%9},{%0,%1,%2,%3};"
                 : "+f"(d0), "+f"(d1), "+f"(d2), "+f"(d3)
                 : "r"(a0), "r"(a1), "r"(a2), "r"(a3), "r"(b0), "r"(b1));
}

// ---------------- prep: split Whh into bf16 hi/lo --------------------------------
__global__ void __launch_bounds__(256) prep_split(
    const float* __restrict__ Whh_f, const float* __restrict__ Whh_b)
{
    int i = blockIdx.x * 256 + threadIdx.x;        // 0 .. 3*NH*NH-1
    bsplit(Whh_f[i], g_whh[0][i], g_whl[0][i]);
    bsplit(Whh_b[i], g_whh[1][i], g_whl[1][i]);
}

// ---------------- generic fp32 tiled GEMM (fc + gate precompute) -----------------
__global__ void __launch_bounds__(256) gemm_bias(
    const float* __restrict__ A, const float* __restrict__ Bw,
    const float* __restrict__ bias, float* __restrict__ C,
    int M, int N, int K)
{
    __shared__ float As[16][65];
    __shared__ float Bs[16][65];
    int tid = threadIdx.x;
    int tx = tid & 15, ty = tid >> 4;
    int m0 = blockIdx.y * 64, n0 = blockIdx.x * 64;
    float acc[4][4] = {};
    for (int k0 = 0; k0 < K; k0 += 16) {
        #pragma unroll
        for (int i = 0; i < 4; i++) {
            int lin = tid + i * 256;
            int m = lin >> 4, k = lin & 15;
            As[k][m] = (k0 + k < K) ? A[(m0 + m) * K + k0 + k] : 0.f;
        }
        #pragma unroll
        for (int i = 0; i < 4; i++) {
            int lin = tid + i * 256;
            int n = lin >> 4, k = lin & 15;
            Bs[k][n] = (k0 + k < K) ? Bw[(n0 + n) * K + k0 + k] : 0.f;
        }
        __syncthreads();
        #pragma unroll
        for (int kk = 0; kk < 16; kk++) {
            float a[4], b[4];
            #pragma unroll
            for (int i = 0; i < 4; i++) a[i] = As[kk][ty * 4 + i];
            #pragma unroll
            for (int j = 0; j < 4; j++) b[j] = Bs[kk][tx * 4 + j];
            #pragma unroll
            for (int i = 0; i < 4; i++)
                #pragma unroll
                for (int j = 0; j < 4; j++) acc[i][j] += a[i] * b[j];
        }
        __syncthreads();
    }
    #pragma unroll
    for (int i = 0; i < 4; i++) {
        int m = m0 + ty * 4 + i;
        #pragma unroll
        for (int j = 0; j < 4; j++) {
            int n = n0 + tx * 4 + j;
            C[m * N + n] = acc[i][j] + bias[n];
        }
    }
}

// ---------------- batchnorm ------------------------------------------------------
__global__ void __launch_bounds__(256) bn_stats()
{
    int c = blockIdx.x;
    float s = 0.f, s2 = 0.f;
    for (int r = threadIdx.x; r < NB; r += 256) {
        float v = g_h0[r * ND + c];
        s += v; s2 += v * v;
    }
    __shared__ float sh[256], sh2[256];
    sh[threadIdx.x] = s; sh2[threadIdx.x] = s2;
    __syncthreads();
    for (int o = 128; o > 0; o >>= 1) {
        if (threadIdx.x < o) {
            sh[threadIdx.x]  += sh[threadIdx.x + o];
            sh2[threadIdx.x] += sh2[threadIdx.x + o];
        }
        __syncthreads();
    }
    if (threadIdx.x == 0) {
        float mu = sh[0] / (float)NB;
        g_stats[c] = mu;
        g_stats[ND + c] = sh2[0] / (float)NB - mu * mu;
    }
}

__global__ void __launch_bounds__(256) bn_apply(
    const float* __restrict__ bn_g, const float* __restrict__ bn_b)
{
    int i = blockIdx.x * 256 + threadIdx.x;
    int c = i & (ND - 1);
    float mu = g_stats[c], var = g_stats[ND + c];
    float v = (g_h0[i] - mu) * rsqrtf(var + 1e-5f) * bn_g[c] + bn_b[c];
    g_h[i] = (v >= 0.f) ? v : 0.2f * v;
}

// ---------------- GRU step via bf16-split tensor-core MMA (clean rewrite) --------
// gh = h @ Whh^T as bf16 GEMM, K' = 3 x 256 (hh*wh + hh*wl + hl*wh), fp32 acc.
// Block: 128 batch x 64 j x 3 gates. Grid (4, 16, 2). No prefetch pipeline.
__global__ void __launch_bounds__(256) gru_mma(
    const float* __restrict__ bhh_f, const float* __restrict__ bhh_b, int t)
{
    const int dir = blockIdx.z;
    const float* bhh = dir ? bhh_b : bhh_f;
    const float* gin = g_gates[dir];
    const int src = t & 1, dst = src ^ 1;
    const float* __restrict__ sfs = g_sf[dir][src];
    const __nv_bfloat16* __restrict__ hh = g_shh[dir][src];
    const __nv_bfloat16* __restrict__ hl = g_shl[dir][src];
    const __nv_bfloat16* __restrict__ wh = g_whh[dir];
    const __nv_bfloat16* __restrict__ wl = g_whl[dir];

    __shared__ __nv_bfloat16 As[128 * 72];   // [m][k] slab, 64 k-cols used
    __shared__ __nv_bfloat16 Bs[192 * 72];   // [g*64+j][k] slab

    const int tid = threadIdx.x;
    const int m0 = blockIdx.y * 128, j0 = blockIdx.x * 64;
    const int warp = tid >> 5, lane = tid & 31;
    const int wm = warp >> 2, wj = warp & 3;
    const int gID = lane >> 2, tig = lane & 3;

    float acc[4][6][4];
    #pragma unroll
    for (int a = 0; a < 4; a++)
        #pragma unroll
        for (int b = 0; b < 6; b++)
            #pragma unroll
            for (int q = 0; q < 4; q++) acc[a][b][q] = 0.f;

    if (t > 0) {
        for (int it = 0; it < 12; it++) {
            const int third = it >> 2;
            const int ks = (it & 3) * 64;
            const __nv_bfloat16* __restrict__ asrc = (third == 2) ? hl : hh;
            const __nv_bfloat16* __restrict__ bsrc = (third == 1) ? wl : wh;
            if (it > 0) __syncthreads();      // previous slab's reads complete
            #pragma unroll
            for (int i = 0; i < 4; i++) {     // A: 128x64 = 1024 uint4
                int u = tid + 256 * i;
                int r = u >> 3, c = (u & 7) << 3;
                *(uint4*)&As[r * 72 + c] =
                    *(const uint4*)&asrc[(m0 + r) * NH + ks + c];
            }
            #pragma unroll
            for (int i = 0; i < 6; i++) {     // B: 192x64 = 1536 uint4
                int u = tid + 256 * i;
                int r = u >> 3, c = (u & 7) << 3;
                *(uint4*)&Bs[r * 72 + c] =
                    *(const uint4*)&bsrc[((r >> 6) * NH + j0 + (r & 63)) * NH + ks + c];
            }
            __syncthreads();
            #pragma unroll
            for (int kk = 0; kk < 4; kk++) {
                const int kb = kk * 16 + tig * 2;
                uint32_t afr[4][4], bfr[6][2];
                #pragma unroll
                for (int mt = 0; mt < 4; mt++) {
                    const __nv_bfloat16* p = As + (wm * 64 + mt * 16 + gID) * 72 + kb;
                    afr[mt][0] = *(const uint32_t*)p;
                    afr[mt][1] = *(const uint32_t*)(p + 8 * 72);
                    afr[mt][2] = *(const uint32_t*)(p + 8);
                    afr[mt][3] = *(const uint32_t*)(p + 8 * 72 + 8);
                }
                #pragma unroll
                for (int g = 0; g < 3; g++)
                    #pragma unroll
                    for (int jn = 0; jn < 2; jn++) {
                        const __nv_bfloat16* p =
                            Bs + (g * 64 + wj * 16 + jn * 8 + gID) * 72 + kb;
                        bfr[g * 2 + jn][0] = *(const uint32_t*)p;
                        bfr[g * 2 + jn][1] = *(const uint32_t*)(p + 8);
                    }
                #pragma unroll
                for (int mt = 0; mt < 4; mt++)
                    #pragma unroll
                    for (int nt = 0; nt < 6; nt++)
                        mma16816(acc[mt][nt][0], acc[mt][nt][1],
                                 acc[mt][nt][2], acc[mt][nt][3],
                                 afr[mt][0], afr[mt][1], afr[mt][2], afr[mt][3],
                                 bfr[nt][0], bfr[nt][1]);
            }
        }
    }

    // epilogue: gates -> h update -> write fp32 state + bf16 hi/lo + gru output
    const int tt = dir ? (NT - 1 - t) : t;
    float* sfd = g_sf[dir][dst];
    __nv_bfloat16* dh = g_shh[dir][dst];
    __nv_bfloat16* dl = g_shl[dir][dst];
    #pragma unroll
    for (int mt = 0; mt < 4; mt++)
        #pragma unroll
        for (int part = 0; part < 2; part++) {
            const int m = m0 + wm * 64 + mt * 16 + gID + part * 8;
            #pragma unroll
            for (int jn = 0; jn < 2; jn++) {
                const int jg = j0 + wj * 16 + jn * 8 + tig * 2;
                #pragma unroll
                for (int cc = 0; cc < 2; cc++) {
                    const int j = jg + cc;
                    float ghr = acc[mt][jn][part * 2 + cc]     + bhh[j];
                    float ghz = acc[mt][2 + jn][part * 2 + cc] + bhh[NH + j];
                    float ghn = acc[mt][4 + jn][part * 2 + cc] + bhh[2 * NH + j];
                    const float* gp = gin + m * 3 * NH + j;
                    float r  = 1.f / (1.f + expf(-(gp[0] + ghr)));
                    float zz = 1.f / (1.f + expf(-(gp[NH] + ghz)));
                    float nn = tanhf(gp[2 * NH] + r * ghn);
                    float hold = (t == 0) ? 0.f : sfs[m * NH + j];
                    float hn = (1.f - zz) * nn + zz * hold;
                    sfd[m * NH + j] = hn;
                    bsplit(hn, dh[m * NH + j], dl[m * NH + j]);
                    g_gru[(m * NT + tt) * (2 * NH) + dir * NH + j] = hn;
                }
            }
        }
}

// ---------------- attention scores (fp32 SIMT, proven) ---------------------------
__global__ void __launch_bounds__(256) attn_score(
    const float* __restrict__ W1, const float* __restrict__ b1,
    const float* __restrict__ W2)
{
    __shared__ float As[16][34];
    __shared__ float Bs[16][256];
    int tid = threadIdx.x;
    int tx = tid & 31, ty = tid >> 5;
    int m0 = blockIdx.x * 32;
    float acc[4][8] = {};
    for (int k0 = 0; k0 < 512; k0 += 16) {
        #pragma unroll
        for (int i = 0; i < 2; i++) {
            int lin = tid + i * 256;
            int m = lin >> 4, k = lin & 15;
            As[k][m] = g_gru[(m0 + m) * 512 + k0 + k];
        }
        #pragma unroll
        for (int i = 0; i < 4; i++) {
            int lin4 = tid + i * 256;
            int n = lin4 >> 2, kq = lin4 & 3;
            float4 v = *(const float4*)&W1[n * 512 + k0 + kq * 4];
            Bs[kq * 4 + 0][n] = v.x;
            Bs[kq * 4 + 1][n] = v.y;
            Bs[kq * 4 + 2][n] = v.z;
            Bs[kq * 4 + 3][n] = v.w;
        }
        __syncthreads();
        #pragma unroll
        for (int kk = 0; kk < 16; kk++) {
            float a[4], b[8];
            #pragma unroll
            for (int r = 0; r < 4; r++) a[r] = As[kk][ty * 4 + r];
            #pragma unroll
            for (int c = 0; c < 8; c++) b[c] = Bs[kk][tx + c * 32];
            #pragma unroll
            for (int r = 0; r < 4; r++)
                #pragma unroll
                for (int c = 0; c < 8; c++) acc[r][c] += a[r] * b[c];
        }
        __syncthreads();
    }
    float partial[4];
    #pragma unroll
    for (int r = 0; r < 4; r++) {
        float s = 0.f;
        #pragma unroll
        for (int c = 0; c < 8; c++) {
            int col = tx + c * 32;
            s += tanhf(acc[r][c] + b1[col]) * W2[col];
        }
        partial[r] = s;
    }
    #pragma unroll
    for (int o = 16; o > 0; o >>= 1)
        #pragma unroll
        for (int r = 0; r < 4; r++)
            partial[r] += __shfl_xor_sync(0xffffffffu, partial[r], o);
    if (tx == 0) {
        #pragma unroll
        for (int r = 0; r < 4; r++) g_s[m0 + ty * 4 + r] = partial[r];
    }
}

// ---------------- softmax over time + context vector -----------------------------
__global__ void __launch_bounds__(256) softmax_ctx()
{
    int b = blockIdx.x;
    __shared__ float w[NT];
    int tid = threadIdx.x;
    if (tid == 0) {
        float mx = -1e30f;
        for (int t = 0; t < NT; t++) {
            float v = g_s[b * NT + t];
            if (v > mx) mx = v;
            w[t] = v;
        }
        float s = 0.f;
        for (int t = 0; t < NT; t++) { w[t] = expf(w[t] - mx); s += w[t]; }
        float inv = 1.f / s;
        for (int t = 0; t < NT; t++) w[t] *= inv;
    }
    __syncthreads();
    for (int d = tid; d < 2 * NH; d += 256) {
        float s = 0.f;
        for (int t = 0; t < NT; t++)
            s += w[t] * g_gru[(b * NT + t) * (2 * NH) + d];
        g_c[b * 2 * NH + d] = s;
    }
}

// ---------------- joint head + forward kinematics --------------------------------
__global__ void __launch_bounds__(256) joints_fk(
    const float* __restrict__ jW, const float* __restrict__ jb,
    float* __restrict__ out)
{
    int w = blockIdx.x * 8 + (threadIdx.x >> 5);
    int lane = threadIdx.x & 31;
    if (w >= NB * NT) return;
    int b = w / NT;
    const float* row  = &g_gru[w * 512];
    const float* crow = &g_c[b * 512];
    float p[6] = {};
    #pragma unroll
    for (int k = 0; k < 16; k++) {
        int d = lane + k * 32;
        float x = row[d] + crow[d];
        #pragma unroll
        for (int j = 0; j < 6; j++) p[j] += x * jW[j * 512 + d];
    }
    #pragma unroll
    for (int o = 16; o > 0; o >>= 1)
        #pragma unroll
        for (int j = 0; j < 6; j++) p[j] += __shfl_xor_sync(0xffffffffu, p[j], o);
    if (lane != 0) return;

    const float LO[6] = {-3.1416f, -1.5708f, -3.1416f, -2.6f, -1.5708f, -1.2f};
    const float UP[6] = { 3.1416f,  1.5708f,  3.1416f,  0.1f,  1.5708f,  1.2f};
    float th[6];
    #pragma unroll
    for (int j = 0; j < 6; j++)
        th[j] = (p[j] + jb[j]) * (UP[j] - LO[j]) + LO[j];

    float c0[3] = {1.f, 0.f, 0.f}, c1[3] = {0.f, 1.f, 0.f}, c2[3] = {0.f, 0.f, 1.f};
    float px = 0.f, py = 0.f, pz = 0.10f;
    float sh2x = 0.f, sh2y = 0.f, sh2z = 0.10f;

    float c, s, tmp;
    c = cosf(th[0]); s = sinf(th[0]);
    #pragma unroll
    for (int i = 0; i < 3; i++) { tmp = c*c0[i] + s*c1[i]; c1[i] = c*c1[i] - s*c0[i]; c0[i] = tmp; }
    c = cosf(th[1]); s = sinf(th[1]);
    #pragma unroll
    for (int i = 0; i < 3; i++) { tmp = c*c1[i] + s*c2[i]; c2[i] = c*c2[i] - s*c1[i]; c1[i] = tmp; }
    c = cosf(th[2]); s = sinf(th[2]);
    #pragma unroll
    for (int i = 0; i < 3; i++) { tmp = c*c0[i] - s*c2[i]; c2[i] = c*c2[i] + s*c0[i]; c0[i] = tmp; }
    px -= 0.25f * c1[0]; py -= 0.25f * c1[1]; pz -= 0.25f * c1[2];
    float fax = px, fay = py, faz = pz;
    c = cosf(th[3]); s = sinf(th[3]);
    #pragma unroll
    for (int i = 0; i < 3; i++) { tmp = c*c1[i] + s*c2[i]; c2[i] = c*c2[i] - s*c1[i]; c1[i] = tmp; }
    c = cosf(th[4]); s = sinf(th[4]);
    #pragma unroll
    for (int i = 0; i < 3; i++) { tmp = c*c0[i] - s*c2[i]; c2[i] = c*c2[i] + s*c0[i]; c0[i] = tmp; }
    px -= 0.25f * c1[0]; py -= 0.25f * c1[1]; pz -= 0.25f * c1[2];
    float wx = px, wy = py, wz = pz;
    c = cosf(th[5]); s = sinf(th[5]);
    #pragma unroll
    for (int i = 0; i < 3; i++) { tmp = c*c1[i] + s*c2[i]; c2[i] = c*c2[i] - s*c1[i]; c1[i] = tmp; }

    float f1x = wx - 0.08f*c1[0] + 0.02f*c2[0];
    float f1y = wy - 0.08f*c1[1] + 0.02f*c2[1];
    float f1z = wz - 0.08f*c1[2] + 0.02f*c2[2];
    float f4x = wx - 0.08f*c1[0] - 0.02f*c2[0];
    float f4y = wy - 0.08f*c1[1] - 0.02f*c2[1];
    float f4z = wz - 0.08f*c1[2] - 0.02f*c2[2];

    float d1x = sh2x - fax, d1y = sh2y - fay, d1z = sh2z - faz;
    float d2x = wx - fax,   d2y = wy - fay,   d2z = wz - faz;
    float bodyL = 0.5f * (sqrtf(d1x*d1x + d1y*d1y + d1z*d1z)
                        + sqrtf(d2x*d2x + d2y*d2y + d2z*d2z));
    float inv = 1.f / bodyL;

    float* o = out + (long)w * 9;
    o[0] = (wx  - sh2x) * inv; o[1] = (wy  - sh2y) * inv; o[2] = (wz  - sh2z) * inv;
    o[3] = (f1x - sh2x) * inv; o[4] = (f1y - sh2y) * inv; o[5] = (f1z - sh2z) * inv;
    o[6] = (f4x - sh2x) * inv; o[7] = (f4y - sh2y) * inv; o[8] = (f4z - sh2z) * inv;
}

// ---------------- host launcher ---------------------------------------------------
extern "C" void kernel_launch(void* const* d_in, const int* in_sizes, int n_in,
                              void* d_out, int out_size)
{
    const float* z       = (const float*)d_in[0];
    const float* W_fc    = (const float*)d_in[1];
    const float* b_fc    = (const float*)d_in[2];
    const float* bn_g    = (const float*)d_in[3];
    const float* bn_b    = (const float*)d_in[4];
    const float* Wih_f   = (const float*)d_in[5];
    const float* Whh_f   = (const float*)d_in[6];
    const float* bih_f   = (const float*)d_in[7];
    const float* bhh_f   = (const float*)d_in[8];
    const float* Wih_b   = (const float*)d_in[9];
    const float* Whh_b   = (const float*)d_in[10];
    const float* bih_b   = (const float*)d_in[11];
    const float* bhh_b   = (const float*)d_in[12];
    const float* attn_W1 = (const float*)d_in[13];
    const float* attn_b1 = (const float*)d_in[14];
    const float* attn_W2 = (const float*)d_in[15];
    const float* joint_W = (const float*)d_in[16];
    const float* joint_b = (const float*)d_in[17];
    float* out = (float*)d_out;

    void *p_h0, *p_h, *p_gates;
    cudaGetSymbolAddress(&p_h0, g_h0);
    cudaGetSymbolAddress(&p_h, g_h);
    cudaGetSymbolAddress(&p_gates, g_gates);
    float* f_h0 = (float*)p_h0;
    float* f_h = (float*)p_h;
    float* f_gates = (float*)p_gates;

    // 0) split Whh into bf16 hi/lo
    prep_split<<<3 * NH * NH / 256, 256>>>(Whh_f, Whh_b);
    // 1) fc
    gemm_bias<<<dim3(ND / 64, NB / 64), 256>>>(z, W_fc, b_fc, f_h0, NB, ND, NDL);
    // 2-3) batchnorm + leaky relu
    bn_stats<<<ND, 256>>>();
    bn_apply<<<NB * ND / 256, 256>>>(bn_g, bn_b);
    // 4) input-gate precompute (x constant over time)
    gemm_bias<<<dim3(3 * NH / 64, NB / 64), 256>>>(f_h, Wih_f, bih_f, f_gates,               NB, 3 * NH, ND);
    gemm_bias<<<dim3(3 * NH / 64, NB / 64), 256>>>(f_h, Wih_b, bih_b, f_gates + NB * 3 * NH, NB, 3 * NH, ND);
    // 5) GRU recurrence (tensor cores, both dirs concurrent)
    for (int t = 0; t < NT; t++)
        gru_mma<<<dim3(NH / 64, NB / 128, 2), 256>>>(bhh_f, bhh_b, t);
    // 6) attention scores (fp32, proven)
    attn_score<<<NB * NT / 32, 256>>>(attn_W1, attn_b1, attn_W2);
    // 7) softmax + context
    softmax_ctx<<<NB, 256>>>();
    // 8) joint head + FK
    joints_fk<<<NB * NT / 8, 256>>>(joint_W, joint_b, out);
}

// round 4
// speedup vs baseline: 1.4417x; 1.2396x over previous
#include <cuda_runtime.h>
#include <cuda_bf16.h>
#include <math.h>
#include <stdint.h>

#define NB   2048
#define NT   60
#define NDL  100
#define ND   512
#define NH   256

// ---------------- scratch (device globals) ----------------
__device__ float g_h0[NB * ND];
__device__ float g_stats[2 * ND];
__device__ float g_h[NB * ND];
__device__ float g_gates[2][NB * 3 * NH];          // x@Wih^T + bih (fp32)
__device__ float g_sf[2][2][NB * NH];              // fp32 GRU state [dir][pingpong]
__device__ __nv_bfloat16 g_shh[2][2][NB * NH];     // bf16 hi copy of state
__device__ __nv_bfloat16 g_shl[2][2][NB * NH];     // bf16 lo copy of state
__device__ __nv_bfloat16 g_whh[2][3 * NH * NH];    // Whh split hi
__device__ __nv_bfloat16 g_whl[2][3 * NH * NH];    // Whh split lo
__device__ __nv_bfloat16 g_w1h[NH * 2 * NH];       // attn_W1 split hi
__device__ __nv_bfloat16 g_w1l[NH * 2 * NH];       // attn_W1 split lo
__device__ float g_gru[NB * NT * 2 * NH];          // concat(gf,gb) fp32 [B,T,512]
__device__ __nv_bfloat16 g_gruh[NB * NT * 2 * NH]; // gru out bf16 hi
__device__ __nv_bfloat16 g_grul[NB * NT * 2 * NH]; // gru out bf16 lo
__device__ float g_s[NB * NT];
__device__ float g_c[NB * 2 * NH];

__device__ __forceinline__ void bsplit(float v, __nv_bfloat16& h, __nv_bfloat16& l) {
    h = __float2bfloat16(v);
    l = __float2bfloat16(v - __bfloat162float(h));
}

__device__ __forceinline__ void mma16816(float& d0, float& d1, float& d2, float& d3,
    uint32_t a0, uint32_t a1, uint32_t a2, uint32_t a3, uint32_t b0, uint32_t b1)
{
    asm volatile("mma.sync.aligned.m16n8k16.row.col.f32.bf16.bf16.f32 "
                 "{%0,%1,%2,%3},{%4,%5,%6,%7},{%8,%9},{%0,%1,%2,%3};"
                 : "+f"(d0), "+f"(d1), "+f"(d2), "+f"(d3)
                 : "r"(a0), "r"(a1), "r"(a2), "r"(a3), "r"(b0), "r"(b1));
}

// ---------------- prep: split Whh and attn_W1 into bf16 hi/lo --------------------
__global__ void __launch_bounds__(256) prep_split(
    const float* __restrict__ Whh_f, const float* __restrict__ Whh_b,
    const float* __restrict__ W1)
{
    int i = blockIdx.x * 256 + threadIdx.x;        // 0 .. 3*NH*NH-1 (196608)
    bsplit(Whh_f[i], g_whh[0][i], g_whl[0][i]);
    bsplit(Whh_b[i], g_whh[1][i], g_whl[1][i]);
    if (i < NH * 2 * NH) bsplit(W1[i], g_w1h[i], g_w1l[i]);
}

// ---------------- generic fp32 tiled GEMM (fc + gate precompute) -----------------
__global__ void __launch_bounds__(256) gemm_bias(
    const float* __restrict__ A, const float* __restrict__ Bw,
    const float* __restrict__ bias, float* __restrict__ C,
    int M, int N, int K)
{
    __shared__ float As[16][65];
    __shared__ float Bs[16][65];
    int tid = threadIdx.x;
    int tx = tid & 15, ty = tid >> 4;
    int m0 = blockIdx.y * 64, n0 = blockIdx.x * 64;
    float acc[4][4] = {};
    for (int k0 = 0; k0 < K; k0 += 16) {
        #pragma unroll
        for (int i = 0; i < 4; i++) {
            int lin = tid + i * 256;
            int m = lin >> 4, k = lin & 15;
            As[k][m] = (k0 + k < K) ? A[(m0 + m) * K + k0 + k] : 0.f;
        }
        #pragma unroll
        for (int i = 0; i < 4; i++) {
            int lin = tid + i * 256;
            int n = lin >> 4, k = lin & 15;
            Bs[k][n] = (k0 + k < K) ? Bw[(n0 + n) * K + k0 + k] : 0.f;
        }
        __syncthreads();
        #pragma unroll
        for (int kk = 0; kk < 16; kk++) {
            float a[4], b[4];
            #pragma unroll
            for (int i = 0; i < 4; i++) a[i] = As[kk][ty * 4 + i];
            #pragma unroll
            for (int j = 0; j < 4; j++) b[j] = Bs[kk][tx * 4 + j];
            #pragma unroll
            for (int i = 0; i < 4; i++)
                #pragma unroll
                for (int j = 0; j < 4; j++) acc[i][j] += a[i] * b[j];
        }
        __syncthreads();
    }
    #pragma unroll
    for (int i = 0; i < 4; i++) {
        int m = m0 + ty * 4 + i;
        #pragma unroll
        for (int j = 0; j < 4; j++) {
            int n = n0 + tx * 4 + j;
            C[m * N + n] = acc[i][j] + bias[n];
        }
    }
}

// ---------------- batchnorm ------------------------------------------------------
__global__ void __launch_bounds__(256) bn_stats()
{
    int c = blockIdx.x;
    float s = 0.f, s2 = 0.f;
    for (int r = threadIdx.x; r < NB; r += 256) {
        float v = g_h0[r * ND + c];
        s += v; s2 += v * v;
    }
    __shared__ float sh[256], sh2[256];
    sh[threadIdx.x] = s; sh2[threadIdx.x] = s2;
    __syncthreads();
    for (int o = 128; o > 0; o >>= 1) {
        if (threadIdx.x < o) {
            sh[threadIdx.x]  += sh[threadIdx.x + o];
            sh2[threadIdx.x] += sh2[threadIdx.x + o];
        }
        __syncthreads();
    }
    if (threadIdx.x == 0) {
        float mu = sh[0] / (float)NB;
        g_stats[c] = mu;
        g_stats[ND + c] = sh2[0] / (float)NB - mu * mu;
    }
}

__global__ void __launch_bounds__(256) bn_apply(
    const float* __restrict__ bn_g, const float* __restrict__ bn_b)
{
    int i = blockIdx.x * 256 + threadIdx.x;
    int c = i & (ND - 1);
    float mu = g_stats[c], var = g_stats[ND + c];
    float v = (g_h0[i] - mu) * rsqrtf(var + 1e-5f) * bn_g[c] + bn_b[c];
    g_h[i] = (v >= 0.f) ? v : 0.2f * v;
}

// ---------------- GRU step via bf16-split tensor-core MMA ------------------------
// Per k-slab split order: (hh*wl), (hh*wh), (hl*wh) -> skip redundant slab loads.
__global__ void __launch_bounds__(256) gru_mma(
    const float* __restrict__ bhh_f, const float* __restrict__ bhh_b, int t)
{
    const int dir = blockIdx.z;
    const float* bhh = dir ? bhh_b : bhh_f;
    const float* gin = g_gates[dir];
    const int src = t & 1, dst = src ^ 1;
    const float* __restrict__ sfs = g_sf[dir][src];
    const __nv_bfloat16* __restrict__ hh = g_shh[dir][src];
    const __nv_bfloat16* __restrict__ hl = g_shl[dir][src];
    const __nv_bfloat16* __restrict__ wh = g_whh[dir];
    const __nv_bfloat16* __restrict__ wl = g_whl[dir];

    __shared__ __nv_bfloat16 As[128 * 72];
    __shared__ __nv_bfloat16 Bs[192 * 72];

    const int tid = threadIdx.x;
    const int m0 = blockIdx.y * 128, j0 = blockIdx.x * 64;
    const int warp = tid >> 5, lane = tid & 31;
    const int wm = warp >> 2, wj = warp & 3;
    const int gID = lane >> 2, tig = lane & 3;

    float acc[4][6][4];
    #pragma unroll
    for (int a = 0; a < 4; a++)
        #pragma unroll
        for (int b = 0; b < 6; b++)
            #pragma unroll
            for (int q = 0; q < 4; q++) acc[a][b][q] = 0.f;

    if (t > 0) {
        for (int it = 0; it < 12; it++) {
            const int ks = (it / 3) * 64;
            const int ph = it % 3;            // 0:(hh,wl) 1:(hh,wh) 2:(hl,wh)
            const bool loadA = (ph != 1);     // A unchanged 0->1
            const bool loadB = (ph != 2);     // B unchanged 1->2
            const __nv_bfloat16* __restrict__ asrc = (ph == 2) ? hl : hh;
            const __nv_bfloat16* __restrict__ bsrc = (ph == 0) ? wl : wh;
            if (it > 0) __syncthreads();
            if (loadA) {
                #pragma unroll
                for (int i = 0; i < 4; i++) {
                    int u = tid + 256 * i;
                    int r = u >> 3, c = (u & 7) << 3;
                    *(uint4*)&As[r * 72 + c] =
                        *(const uint4*)&asrc[(m0 + r) * NH + ks + c];
                }
            }
            if (loadB) {
                #pragma unroll
                for (int i = 0; i < 6; i++) {
                    int u = tid + 256 * i;
                    int r = u >> 3, c = (u & 7) << 3;
                    *(uint4*)&Bs[r * 72 + c] =
                        *(const uint4*)&bsrc[((r >> 6) * NH + j0 + (r & 63)) * NH + ks + c];
                }
            }
            __syncthreads();
            #pragma unroll
            for (int kk = 0; kk < 4; kk++) {
                const int kb = kk * 16 + tig * 2;
                uint32_t afr[4][4], bfr[6][2];
                #pragma unroll
                for (int mt = 0; mt < 4; mt++) {
                    const __nv_bfloat16* p = As + (wm * 64 + mt * 16 + gID) * 72 + kb;
                    afr[mt][0] = *(const uint32_t*)p;
                    afr[mt][1] = *(const uint32_t*)(p + 8 * 72);
                    afr[mt][2] = *(const uint32_t*)(p + 8);
                    afr[mt][3] = *(const uint32_t*)(p + 8 * 72 + 8);
                }
                #pragma unroll
                for (int g = 0; g < 3; g++)
                    #pragma unroll
                    for (int jn = 0; jn < 2; jn++) {
                        const __nv_bfloat16* p =
                            Bs + (g * 64 + wj * 16 + jn * 8 + gID) * 72 + kb;
                        bfr[g * 2 + jn][0] = *(const uint32_t*)p;
                        bfr[g * 2 + jn][1] = *(const uint32_t*)(p + 8);
                    }
                #pragma unroll
                for (int mt = 0; mt < 4; mt++)
                    #pragma unroll
                    for (int nt = 0; nt < 6; nt++)
                        mma16816(acc[mt][nt][0], acc[mt][nt][1],
                                 acc[mt][nt][2], acc[mt][nt][3],
                                 afr[mt][0], afr[mt][1], afr[mt][2], afr[mt][3],
                                 bfr[nt][0], bfr[nt][1]);
            }
        }
    }

    // epilogue
    const int tt = dir ? (NT - 1 - t) : t;
    float* sfd = g_sf[dir][dst];
    __nv_bfloat16* dh = g_shh[dir][dst];
    __nv_bfloat16* dl = g_shl[dir][dst];
    #pragma unroll
    for (int mt = 0; mt < 4; mt++)
        #pragma unroll
        for (int part = 0; part < 2; part++) {
            const int m = m0 + wm * 64 + mt * 16 + gID + part * 8;
            #pragma unroll
            for (int jn = 0; jn < 2; jn++) {
                const int jg = j0 + wj * 16 + jn * 8 + tig * 2;
                #pragma unroll
                for (int cc = 0; cc < 2; cc++) {
                    const int j = jg + cc;
                    float ghr = acc[mt][jn][part * 2 + cc]     + bhh[j];
                    float ghz = acc[mt][2 + jn][part * 2 + cc] + bhh[NH + j];
                    float ghn = acc[mt][4 + jn][part * 2 + cc] + bhh[2 * NH + j];
                    const float* gp = gin + m * 3 * NH + j;
                    float r  = 1.f / (1.f + expf(-(gp[0] + ghr)));
                    float zz = 1.f / (1.f + expf(-(gp[NH] + ghz)));
                    float nn = tanhf(gp[2 * NH] + r * ghn);
                    float hold = (t == 0) ? 0.f : sfs[m * NH + j];
                    float hn = (1.f - zz) * nn + zz * hold;
                    sfd[m * NH + j] = hn;
                    __nv_bfloat16 bh, bl;
                    bsplit(hn, bh, bl);
                    dh[m * NH + j] = bh;
                    dl[m * NH + j] = bl;
                    const int go = (m * NT + tt) * (2 * NH) + dir * NH + j;
                    g_gru[go]  = hn;
                    g_gruh[go] = bh;
                    g_grul[go] = bl;
                }
            }
        }
}

// ---------------- attention scores via bf16-split MMA ----------------------------
// s[m] = W2 . tanh(W1 @ gru[m] + b1). M=NB*NT, N=256, K'=3x512.
// Block: 64 m-rows x 256 n. Split order per ks: (gh*wl),(gh*wh),(gl*wh).
__global__ void __launch_bounds__(256) attn_mma(
    const float* __restrict__ b1, const float* __restrict__ W2)
{
    __shared__ __nv_bfloat16 As[64 * 72];
    __shared__ __nv_bfloat16 Bs[256 * 72];
    __shared__ float red[64];

    const int tid = threadIdx.x;
    const int m0 = blockIdx.x * 64;
    const int warp = tid >> 5, lane = tid & 31;
    const int wm = warp >> 2, wj = warp & 3;      // wm: 2 m-halves, wj: 4 n-quads
    const int gID = lane >> 2, tig = lane & 3;
    if (tid < 64) red[tid] = 0.f;

    float acc[2][8][4];
    #pragma unroll
    for (int a = 0; a < 2; a++)
        #pragma unroll
        for (int b = 0; b < 8; b++)
            #pragma unroll
            for (int q = 0; q < 4; q++) acc[a][b][q] = 0.f;

    for (int it = 0; it < 24; it++) {
        const int ks = (it / 3) * 64;
        const int ph = it % 3;
        const bool loadA = (ph != 1);
        const bool loadB = (ph != 2);
        const __nv_bfloat16* __restrict__ asrc = (ph == 2) ? g_grul : g_gruh;
        const __nv_bfloat16* __restrict__ bsrc = (ph == 0) ? g_w1l : g_w1h;
        if (it > 0) __syncthreads();
        if (loadA) {
            #pragma unroll
            for (int i = 0; i < 2; i++) {      // 64x64 = 512 uint4
                int u = tid + 256 * i;
                int r = u >> 3, c = (u & 7) << 3;
                *(uint4*)&As[r * 72 + c] =
                    *(const uint4*)&asrc[(m0 + r) * 512 + ks + c];
            }
        }
        if (loadB) {
            #pragma unroll
            for (int i = 0; i < 8; i++) {      // 256x64 = 2048 uint4
                int u = tid + 256 * i;
                int r = u >> 3, c = (u & 7) << 3;
                *(uint4*)&Bs[r * 72 + c] =
                    *(const uint4*)&bsrc[r * 512 + ks + c];
            }
        }
        __syncthreads();
        #pragma unroll
        for (int kk = 0; kk < 4; kk++) {
            const int kb = kk * 16 + tig * 2;
            uint32_t afr[2][4], bfr[8][2];
            #pragma unroll
            for (int mt = 0; mt < 2; mt++) {
                const __nv_bfloat16* p = As + (wm * 32 + mt * 16 + gID) * 72 + kb;
                afr[mt][0] = *(const uint32_t*)p;
                afr[mt][1] = *(const uint32_t*)(p + 8 * 72);
                afr[mt][2] = *(const uint32_t*)(p + 8);
                afr[mt][3] = *(const uint32_t*)(p + 8 * 72 + 8);
            }
            #pragma unroll
            for (int nt = 0; nt < 8; nt++) {
                const __nv_bfloat16* p = Bs + (wj * 64 + nt * 8 + gID) * 72 + kb;
                bfr[nt][0] = *(const uint32_t*)p;
                bfr[nt][1] = *(const uint32_t*)(p + 8);
            }
            #pragma unroll
            for (int mt = 0; mt < 2; mt++)
                #pragma unroll
                for (int nt = 0; nt < 8; nt++)
                    mma16816(acc[mt][nt][0], acc[mt][nt][1],
                             acc[mt][nt][2], acc[mt][nt][3],
                             afr[mt][0], afr[mt][1], afr[mt][2], afr[mt][3],
                             bfr[nt][0], bfr[nt][1]);
        }
    }

    // epilogue: tanh(.+b1)*W2, reduce over this warp's 64 n-cols, combine in smem
    #pragma unroll
    for (int mt = 0; mt < 2; mt++)
        #pragma unroll
        for (int part = 0; part < 2; part++) {
            float s = 0.f;
            #pragma unroll
            for (int nt = 0; nt < 8; nt++)
                #pragma unroll
                for (int cc = 0; cc < 2; cc++) {
                    int n = wj * 64 + nt * 8 + tig * 2 + cc;
                    s += tanhf(acc[mt][nt][part * 2 + cc] + b1[n]) * W2[n];
                }
            s += __shfl_xor_sync(0xffffffffu, s, 1);
            s += __shfl_xor_sync(0xffffffffu, s, 2);
            if (tig == 0)
                atomicAdd(&red[wm * 32 + mt * 16 + gID + part * 8], s);
        }
    __syncthreads();
    if (tid < 64) g_s[m0 + tid] = red[tid];
}

// ---------------- softmax over time + context vector -----------------------------
__global__ void __launch_bounds__(256) softmax_ctx()
{
    int b = blockIdx.x;
    __shared__ float w[NT];
    int tid = threadIdx.x;
    if (tid == 0) {
        float mx = -1e30f;
        for (int t = 0; t < NT; t++) {
            float v = g_s[b * NT + t];
            if (v > mx) mx = v;
            w[t] = v;
        }
        float s = 0.f;
        for (int t = 0; t < NT; t++) { w[t] = expf(w[t] - mx); s += w[t]; }
        float inv = 1.f / s;
        for (int t = 0; t < NT; t++) w[t] *= inv;
    }
    __syncthreads();
    for (int d = tid; d < 2 * NH; d += 256) {
        float s = 0.f;
        for (int t = 0; t < NT; t++)
            s += w[t] * g_gru[(b * NT + t) * (2 * NH) + d];
        g_c[b * 2 * NH + d] = s;
    }
}

// ---------------- joint head + forward kinematics --------------------------------
__global__ void __launch_bounds__(256) joints_fk(
    const float* __restrict__ jW, const float* __restrict__ jb,
    float* __restrict__ out)
{
    int w = blockIdx.x * 8 + (threadIdx.x >> 5);
    int lane = threadIdx.x & 31;
    if (w >= NB * NT) return;
    int b = w / NT;
    const float* row  = &g_gru[w * 512];
    const float* crow = &g_c[b * 512];
    float p[6] = {};
    #pragma unroll
    for (int k = 0; k < 16; k++) {
        int d = lane + k * 32;
        float x = row[d] + crow[d];
        #pragma unroll
        for (int j = 0; j < 6; j++) p[j] += x * jW[j * 512 + d];
    }
    #pragma unroll
    for (int o = 16; o > 0; o >>= 1)
        #pragma unroll
        for (int j = 0; j < 6; j++) p[j] += __shfl_xor_sync(0xffffffffu, p[j], o);
    if (lane != 0) return;

    const float LO[6] = {-3.1416f, -1.5708f, -3.1416f, -2.6f, -1.5708f, -1.2f};
    const float UP[6] = { 3.1416f,  1.5708f,  3.1416f,  0.1f,  1.5708f,  1.2f};
    float th[6];
    #pragma unroll
    for (int j = 0; j < 6; j++)
        th[j] = (p[j] + jb[j]) * (UP[j] - LO[j]) + LO[j];

    float c0[3] = {1.f, 0.f, 0.f}, c1[3] = {0.f, 1.f, 0.f}, c2[3] = {0.f, 0.f, 1.f};
    float px = 0.f, py = 0.f, pz = 0.10f;
    float sh2x = 0.f, sh2y = 0.f, sh2z = 0.10f;

    float c, s, tmp;
    c = cosf(th[0]); s = sinf(th[0]);
    #pragma unroll
    for (int i = 0; i < 3; i++) { tmp = c*c0[i] + s*c1[i]; c1[i] = c*c1[i] - s*c0[i]; c0[i] = tmp; }
    c = cosf(th[1]); s = sinf(th[1]);
    #pragma unroll
    for (int i = 0; i < 3; i++) { tmp = c*c1[i] + s*c2[i]; c2[i] = c*c2[i] - s*c1[i]; c1[i] = tmp; }
    c = cosf(th[2]); s = sinf(th[2]);
    #pragma unroll
    for (int i = 0; i < 3; i++) { tmp = c*c0[i] - s*c2[i]; c2[i] = c*c2[i] + s*c0[i]; c0[i] = tmp; }
    px -= 0.25f * c1[0]; py -= 0.25f * c1[1]; pz -= 0.25f * c1[2];
    float fax = px, fay = py, faz = pz;
    c = cosf(th[3]); s = sinf(th[3]);
    #pragma unroll
    for (int i = 0; i < 3; i++) { tmp = c*c1[i] + s*c2[i]; c2[i] = c*c2[i] - s*c1[i]; c1[i] = tmp; }
    c = cosf(th[4]); s = sinf(th[4]);
    #pragma unroll
    for (int i = 0; i < 3; i++) { tmp = c*c0[i] - s*c2[i]; c2[i] = c*c2[i] + s*c0[i]; c0[i] = tmp; }
    px -= 0.25f * c1[0]; py -= 0.25f * c1[1]; pz -= 0.25f * c1[2];
    float wx = px, wy = py, wz = pz;
    c = cosf(th[5]); s = sinf(th[5]);
    #pragma unroll
    for (int i = 0; i < 3; i++) { tmp = c*c1[i] + s*c2[i]; c2[i] = c*c2[i] - s*c1[i]; c1[i] = tmp; }

    float f1x = wx - 0.08f*c1[0] + 0.02f*c2[0];
    float f1y = wy - 0.08f*c1[1] + 0.02f*c2[1];
    float f1z = wz - 0.08f*c1[2] + 0.02f*c2[2];
    float f4x = wx - 0.08f*c1[0] - 0.02f*c2[0];
    float f4y = wy - 0.08f*c1[1] - 0.02f*c2[1];
    float f4z = wz - 0.08f*c1[2] - 0.02f*c2[2];

    float d1x = sh2x - fax, d1y = sh2y - fay, d1z = sh2z - faz;
    float d2x = wx - fax,   d2y = wy - fay,   d2z = wz - faz;
    float bodyL = 0.5f * (sqrtf(d1x*d1x + d1y*d1y + d1z*d1z)
                        + sqrtf(d2x*d2x + d2y*d2y + d2z*d2z));
    float inv = 1.f / bodyL;

    float* o = out + (long)w * 9;
    o[0] = (wx  - sh2x) * inv; o[1] = (wy  - sh2y) * inv; o[2] = (wz  - sh2z) * inv;
    o[3] = (f1x - sh2x) * inv; o[4] = (f1y - sh2y) * inv; o[5] = (f1z - sh2z) * inv;
    o[6] = (f4x - sh2x) * inv; o[7] = (f4y - sh2y) * inv; o[8] = (f4z - sh2z) * inv;
}

// ---------------- host launcher ---------------------------------------------------
extern "C" void kernel_launch(void* const* d_in, const int* in_sizes, int n_in,
                              void* d_out, int out_size)
{
    const float* z       = (const float*)d_in[0];
    const float* W_fc    = (const float*)d_in[1];
    const float* b_fc    = (const float*)d_in[2];
    const float* bn_g    = (const float*)d_in[3];
    const float* bn_b    = (const float*)d_in[4];
    const float* Wih_f   = (const float*)d_in[5];
    const float* Whh_f   = (const float*)d_in[6];
    const float* bih_f   = (const float*)d_in[7];
    const float* bhh_f   = (const float*)d_in[8];
    const float* Wih_b   = (const float*)d_in[9];
    const float* Whh_b   = (const float*)d_in[10];
    const float* bih_b   = (const float*)d_in[11];
    const float* bhh_b   = (const float*)d_in[12];
    const float* attn_W1 = (const float*)d_in[13];
    const float* attn_b1 = (const float*)d_in[14];
    const float* attn_W2 = (const float*)d_in[15];
    const float* joint_W = (const float*)d_in[16];
    const float* joint_b = (const float*)d_in[17];
    float* out = (float*)d_out;

    void *p_h0, *p_h, *p_gates;
    cudaGetSymbolAddress(&p_h0, g_h0);
    cudaGetSymbolAddress(&p_h, g_h);
    cudaGetSymbolAddress(&p_gates, g_gates);
    float* f_h0 = (float*)p_h0;
    float* f_h = (float*)p_h;
    float* f_gates = (float*)p_gates;

    // 0) split weights
    prep_split<<<3 * NH * NH / 256, 256>>>(Whh_f, Whh_b, attn_W1);
    // 1) fc
    gemm_bias<<<dim3(ND / 64, NB / 64), 256>>>(z, W_fc, b_fc, f_h0, NB, ND, NDL);
    // 2-3) batchnorm + leaky relu
    bn_stats<<<ND, 256>>>();
    bn_apply<<<NB * ND / 256, 256>>>(bn_g, bn_b);
    // 4) input-gate precompute
    gemm_bias<<<dim3(3 * NH / 64, NB / 64), 256>>>(f_h, Wih_f, bih_f, f_gates,               NB, 3 * NH, ND);
    gemm_bias<<<dim3(3 * NH / 64, NB / 64), 256>>>(f_h, Wih_b, bih_b, f_gates + NB * 3 * NH, NB, 3 * NH, ND);
    // 5) GRU recurrence (tensor cores)
    for (int t = 0; t < NT; t++)
        gru_mma<<<dim3(NH / 64, NB / 128, 2), 256>>>(bhh_f, bhh_b, t);
    // 6) attention scores (tensor cores)
    attn_mma<<<NB * NT / 64, 256>>>(attn_b1, attn_W2);
    // 7) softmax + context
    softmax_ctx<<<NB, 256>>>();
    // 8) joint head + FK
    joints_fk<<<NB * NT / 8, 256>>>(joint_W, joint_b, out);
}